// round 8
// baseline (speedup 1.0000x reference)
#include <cuda_runtime.h>
#include <cuda_fp16.h>
#include <mma.h>

using namespace nvcuda;

// SGC K=2:  out = Prop(Prop(x @ W)) + b   (projection commuted to the front)
// - wmma fp16 tensor-core GEMM (fp32 accumulate)
// - pull aggregation over per-call CSR, rows padded to 4 for int4 index loads
// - features stored fp16 (half2/lane), fp32 accumulate
// - 7 launches: deg, scan1, scan23, scatter, gemm, pull1, pull2
//   (g_deg re-zeroed at end of pull2; device globals start zero-initialized)

#define NN 100000
#define EE 3200000
#define IN_F 256
#define OUT_F 64
#define SCAN_B 1024
#define SCAN_NB ((NN + SCAN_B - 1) / SCAN_B)   // 98
#define CSR_CAP (EE + 3 * NN + 4)

// ---------------- scratch (static device globals; no allocation) -------------
__device__ __half g_y0h[NN * OUT_F];  // (x@W)*norm, fp16
__device__ __half g_z1h[NN * OUT_F];  // round-1 result * norm^2, fp16
__device__ float  g_norm[NN];
__device__ int    g_deg[NN];          // true degree (zeroed at end of each call)
__device__ int    g_off[NN];          // padded CSR row offsets (mult of 4)
__device__ int    g_cur[NN];          // scatter cursors
__device__ int    g_csr[CSR_CAP];     // src ids grouped by dst (rows padded to 4)
__device__ int    g_part[SCAN_NB];    // scan partials

// ---------------- degree histogram (g_deg must be zero on entry) -------------
__global__ void deg_kernel(const int* __restrict__ dst, int E) {
    int e = blockIdx.x * blockDim.x + threadIdx.x;
    if (e < E) atomicAdd(&g_deg[dst[e]], 1);
}

// ---------------- scan stage 1: per-block sums of PADDED degrees -------------
__global__ void __launch_bounds__(SCAN_B) scan1_kernel(int N) {
    __shared__ int sh[SCAN_B];
    int t = threadIdx.x;
    int i = blockIdx.x * SCAN_B + t;
    int v = (i < N) ? ((g_deg[i] + 3) & ~3) : 0;
    sh[t] = v;
    __syncthreads();
    for (int o = SCAN_B / 2; o > 0; o >>= 1) {
        if (t < o) sh[t] += sh[t + o];
        __syncthreads();
    }
    if (t == 0) g_part[blockIdx.x] = sh[0];
}

// ---------------- scan stage 2+3 fused: padded exclusive scan + norm ---------
__global__ void __launch_bounds__(SCAN_B) scan23_kernel(int N) {
    __shared__ int sh[SCAN_B];
    __shared__ int pp[128];
    __shared__ int sbase;
    int t = threadIdx.x;
    int i = blockIdx.x * SCAN_B + t;
    int dv = (i < N) ? g_deg[i] : 0;
    int vp = (dv + 3) & ~3;
    sh[t] = vp;
    if (t < 128) pp[t] = (t < blockIdx.x && t < SCAN_NB) ? g_part[t] : 0;
    __syncthreads();
    if (t == 0) {
        int run = 0;
        #pragma unroll
        for (int k = 0; k < 128; k++) run += pp[k];
        sbase = run;
    }
    for (int o = 1; o < SCAN_B; o <<= 1) {
        int a = (t >= o) ? sh[t - o] : 0;
        __syncthreads();
        sh[t] += a;
        __syncthreads();
    }
    if (i < N) {
        int excl = sh[t] - vp + sbase;
        g_off[i] = excl;
        g_cur[i] = excl;
        g_norm[i] = rsqrtf(fmaxf((float)dv, 1.0f));
    }
}

// ---------------- CSR fill: group src by dst ---------------------------------
__global__ void scatter_kernel(const int* __restrict__ src,
                               const int* __restrict__ dst, int E) {
    int e = blockIdx.x * blockDim.x + threadIdx.x;
    if (e < E) {
        int pos = atomicAdd(&g_cur[dst[e]], 1);
        g_csr[pos] = src[e];
    }
}

// ---------------- y0h = fp16((x @ W) * norm)  via wmma -----------------------
// block: 64 rows x 64 cols, 8 warps in 4x2 grid, each warp 16x32 (2 frags)
__global__ void __launch_bounds__(256) gemm_kernel(const float* __restrict__ x,
                                                   const float* __restrict__ W,
                                                   int N) {
    __shared__ __half As[64][72];    // x tile (fp16), padded ld
    __shared__ __half Bs[64][72];    // W chunk [k][n]
    __shared__ float  Os[64][68];    // fp32 result staging

    const int t = threadIdx.x;
    const int w = t >> 5;
    const int wr = w >> 1;           // 0..3 (row group)
    const int wc = w & 1;            // 0..1 (col group)
    const int rowbase = blockIdx.x * 64;

    wmma::fragment<wmma::accumulator, 16, 16, 16, float> acc0, acc1;
    wmma::fill_fragment(acc0, 0.0f);
    wmma::fill_fragment(acc1, 0.0f);

    for (int kc = 0; kc < IN_F; kc += 64) {
        #pragma unroll
        for (int i = 0; i < 16; i++) {
            int lin = t + i * 256;
            int r = lin >> 6;
            int c = lin & 63;
            int gr = rowbase + r;
            float xv = (gr < N) ? x[(long long)gr * IN_F + kc + c] : 0.0f;
            As[r][c] = __float2half(xv);
            Bs[r][c] = __float2half(W[(kc + r) * OUT_F + c]);
        }
        __syncthreads();

        #pragma unroll
        for (int ks = 0; ks < 4; ks++) {
            wmma::fragment<wmma::matrix_a, 16, 16, 16, __half, wmma::row_major> af;
            wmma::load_matrix_sync(af, &As[wr * 16][ks * 16], 72);
            wmma::fragment<wmma::matrix_b, 16, 16, 16, __half, wmma::row_major> bf0, bf1;
            wmma::load_matrix_sync(bf0, &Bs[ks * 16][wc * 32], 72);
            wmma::load_matrix_sync(bf1, &Bs[ks * 16][wc * 32 + 16], 72);
            wmma::mma_sync(acc0, af, bf0, acc0);
            wmma::mma_sync(acc1, af, bf1, acc1);
        }
        __syncthreads();
    }

    wmma::store_matrix_sync(&Os[wr * 16][wc * 32], acc0, 68, wmma::mem_row_major);
    wmma::store_matrix_sync(&Os[wr * 16][wc * 32 + 16], acc1, 68, wmma::mem_row_major);
    __syncthreads();

    // scale by norm, convert to fp16, write (4 threads/row, 16 cols each)
    int r = t >> 2;
    int c0 = (t & 3) * 16;
    int gr = rowbase + r;
    if (gr < N) {
        float nm = g_norm[gr];
        __half2* p = (__half2*)&g_y0h[(long long)gr * OUT_F + c0];
        #pragma unroll
        for (int k = 0; k < 8; k++) {
            p[k] = __floats2half2_rn(Os[r][c0 + 2 * k] * nm,
                                     Os[r][c0 + 2 * k + 1] * nm);
        }
    }
}

// ---------------- pull round 1: z1h[i] = fp16((sum y0h[s]) * norm[i]^2) ------
// one warp per node; int4 index loads (rows padded to 4); 8-wide unroll for MLP
__global__ void __launch_bounds__(256) pull1_kernel(int N) {
    int warp = (blockIdx.x * blockDim.x + threadIdx.x) >> 5;
    if (warp >= N) return;
    int lane = threadIdx.x & 31;
    int base = g_off[warp];
    int deg = g_deg[warp];
    const __half2* yp = (const __half2*)g_y0h;
    const int* cp = g_csr + base;

    float ax = 0.0f, ay = 0.0f;
    int j = 0;
    for (; j + 8 <= deg; j += 8) {
        int4 sA = __ldg((const int4*)(cp + j));
        int4 sB = __ldg((const int4*)(cp + j + 4));
        float2 v0 = __half22float2(__ldg(yp + sA.x * 32 + lane));
        float2 v1 = __half22float2(__ldg(yp + sA.y * 32 + lane));
        float2 v2 = __half22float2(__ldg(yp + sA.z * 32 + lane));
        float2 v3 = __half22float2(__ldg(yp + sA.w * 32 + lane));
        float2 v4 = __half22float2(__ldg(yp + sB.x * 32 + lane));
        float2 v5 = __half22float2(__ldg(yp + sB.y * 32 + lane));
        float2 v6 = __half22float2(__ldg(yp + sB.z * 32 + lane));
        float2 v7 = __half22float2(__ldg(yp + sB.w * 32 + lane));
        ax += (v0.x + v1.x) + (v2.x + v3.x) + ((v4.x + v5.x) + (v6.x + v7.x));
        ay += (v0.y + v1.y) + (v2.y + v3.y) + ((v4.y + v5.y) + (v6.y + v7.y));
    }
    for (; j + 4 <= deg; j += 4) {
        int4 s = __ldg((const int4*)(cp + j));
        float2 v0 = __half22float2(__ldg(yp + s.x * 32 + lane));
        float2 v1 = __half22float2(__ldg(yp + s.y * 32 + lane));
        float2 v2 = __half22float2(__ldg(yp + s.z * 32 + lane));
        float2 v3 = __half22float2(__ldg(yp + s.w * 32 + lane));
        ax += v0.x + v1.x + v2.x + v3.x;
        ay += v0.y + v1.y + v2.y + v3.y;
    }
    if (j < deg) {
        int4 s = __ldg((const int4*)(cp + j));  // padded row: in-bounds
        {            float2 v = __half22float2(__ldg(yp + s.x * 32 + lane)); ax += v.x; ay += v.y; }
        if (j + 1 < deg) { float2 v = __half22float2(__ldg(yp + s.y * 32 + lane)); ax += v.x; ay += v.y; }
        if (j + 2 < deg) { float2 v = __half22float2(__ldg(yp + s.z * 32 + lane)); ax += v.x; ay += v.y; }
    }
    float nm = g_norm[warp];
    nm *= nm;
    ((__half2*)g_z1h)[warp * 32 + lane] = __floats2half2_rn(ax * nm, ay * nm);
}

// ---------------- pull round 2: out[i] = (sum z1h[s]) * norm[i] + b ----------
// also re-zeroes g_deg[node] for the next call (deterministic per-call state)
__global__ void __launch_bounds__(256) pull2_kernel(const float* __restrict__ b,
                                                    float* __restrict__ out, int N) {
    int warp = (blockIdx.x * blockDim.x + threadIdx.x) >> 5;
    if (warp >= N) return;
    int lane = threadIdx.x & 31;
    int base = g_off[warp];
    int deg = g_deg[warp];
    __syncwarp();
    if (lane == 0) g_deg[warp] = 0;   // reset for next call
    const __half2* zp = (const __half2*)g_z1h;
    const int* cp = g_csr + base;

    float ax = 0.0f, ay = 0.0f;
    int j = 0;
    for (; j + 8 <= deg; j += 8) {
        int4 sA = __ldg((const int4*)(cp + j));
        int4 sB = __ldg((const int4*)(cp + j + 4));
        float2 v0 = __half22float2(__ldg(zp + sA.x * 32 + lane));
        float2 v1 = __half22float2(__ldg(zp + sA.y * 32 + lane));
        float2 v2 = __half22float2(__ldg(zp + sA.z * 32 + lane));
        float2 v3 = __half22float2(__ldg(zp + sA.w * 32 + lane));
        float2 v4 = __half22float2(__ldg(zp + sB.x * 32 + lane));
        float2 v5 = __half22float2(__ldg(zp + sB.y * 32 + lane));
        float2 v6 = __half22float2(__ldg(zp + sB.z * 32 + lane));
        float2 v7 = __half22float2(__ldg(zp + sB.w * 32 + lane));
        ax += (v0.x + v1.x) + (v2.x + v3.x) + ((v4.x + v5.x) + (v6.x + v7.x));
        ay += (v0.y + v1.y) + (v2.y + v3.y) + ((v4.y + v5.y) + (v6.y + v7.y));
    }
    for (; j + 4 <= deg; j += 4) {
        int4 s = __ldg((const int4*)(cp + j));
        float2 v0 = __half22float2(__ldg(zp + s.x * 32 + lane));
        float2 v1 = __half22float2(__ldg(zp + s.y * 32 + lane));
        float2 v2 = __half22float2(__ldg(zp + s.z * 32 + lane));
        float2 v3 = __half22float2(__ldg(zp + s.w * 32 + lane));
        ax += v0.x + v1.x + v2.x + v3.x;
        ay += v0.y + v1.y + v2.y + v3.y;
    }
    if (j < deg) {
        int4 s = __ldg((const int4*)(cp + j));
        {            float2 v = __half22float2(__ldg(zp + s.x * 32 + lane)); ax += v.x; ay += v.y; }
        if (j + 1 < deg) { float2 v = __half22float2(__ldg(zp + s.y * 32 + lane)); ax += v.x; ay += v.y; }
        if (j + 2 < deg) { float2 v = __half22float2(__ldg(zp + s.z * 32 + lane)); ax += v.x; ay += v.y; }
    }
    float nm = g_norm[warp];
    float2 bb = __ldg((const float2*)b + lane);
    ((float2*)out)[warp * 32 + lane] =
        make_float2(ax * nm + bb.x, ay * nm + bb.y);
}

// ---------------- launch -----------------------------------------------------
extern "C" void kernel_launch(void* const* d_in, const int* in_sizes, int n_in,
                              void* d_out, int out_size) {
    const float* x   = (const float*)d_in[0];
    const int*   src = (const int*)d_in[1];
    const int*   dst = (const int*)d_in[2];
    const float* W   = (const float*)d_in[3];
    const float* b   = (const float*)d_in[4];
    float*       out = (float*)d_out;

    const int N = in_sizes[0] / IN_F;   // 100000
    const int E = in_sizes[1];          // 3200000

    // CSR build (padded rows).  g_deg is zero on entry (zero-init at load,
    // re-zeroed by pull2 at the end of every call).
    deg_kernel<<<(E + 255) / 256, 256>>>(dst, E);
    scan1_kernel<<<SCAN_NB, SCAN_B>>>(N);
    scan23_kernel<<<SCAN_NB, SCAN_B>>>(N);
    scatter_kernel<<<(E + 255) / 256, 256>>>(src, dst, E);

    // tensor-core projection (scaled by norm at write, fp16 out)
    gemm_kernel<<<(N + 63) / 64, 256>>>(x, W, N);

    // two pull rounds (warp per node)
    const int pb = 256;
    const int pgrid = (N * 32 + pb - 1) / pb;
    pull1_kernel<<<pgrid, pb>>>(N);
    pull2_kernel<<<pgrid, pb>>>(b, out, N);
}

// round 9
// speedup vs baseline: 1.5537x; 1.5537x over previous
#include <cuda_runtime.h>
#include <cuda_fp16.h>
#include <mma.h>

using namespace nvcuda;

// SGC K=2:  out = Prop(Prop(x @ W)) + b   (projection commuted to the front)
// - wmma fp16 tensor-core GEMM (fp32 accumulate)
// - pull aggregation over per-call CSR, rows padded to 4 for int4 index loads
// - features stored fp16 (half2/lane), fp32 accumulate
// - deg/scatter process 4 edges/thread (ILP over atomic latency)

#define NN 100000
#define EE 3200000
#define IN_F 256
#define OUT_F 64
#define SCAN_B 1024
#define SCAN_NB ((NN + SCAN_B - 1) / SCAN_B)   // 98
#define CSR_CAP (EE + 3 * NN + 4)

// ---------------- scratch (static device globals; no allocation) -------------
__device__ __half g_y0h[NN * OUT_F];  // (x@W)*norm, fp16
__device__ __half g_z1h[NN * OUT_F];  // round-1 result * norm^2, fp16
__device__ float  g_norm[NN];
__device__ int    g_deg[NN];          // true degree
__device__ int    g_off[NN];          // padded CSR row offsets (mult of 4)
__device__ int    g_cur[NN];          // scatter cursors
__device__ int    g_csr[CSR_CAP];     // src ids grouped by dst (rows padded to 4)
__device__ int    g_part[SCAN_NB];    // scan partials

// ---------------- degree histogram: 4 edges/thread, no-return atomics --------
__global__ void deg_kernel(const int* __restrict__ dst, int E) {
    int t = blockIdx.x * blockDim.x + threadIdx.x;
    int e = t * 4;
    if (e + 4 <= E) {
        int4 d = __ldg((const int4*)(dst + e));
        atomicAdd(&g_deg[d.x], 1);
        atomicAdd(&g_deg[d.y], 1);
        atomicAdd(&g_deg[d.z], 1);
        atomicAdd(&g_deg[d.w], 1);
    } else {
        for (int k = e; k < E; k++) atomicAdd(&g_deg[dst[k]], 1);
    }
}

// ---------------- scan stage 1: per-block sums of PADDED degrees -------------
__global__ void __launch_bounds__(SCAN_B) scan1_kernel(int N) {
    __shared__ int sh[SCAN_B];
    int t = threadIdx.x;
    int i = blockIdx.x * SCAN_B + t;
    int v = (i < N) ? ((g_deg[i] + 3) & ~3) : 0;
    sh[t] = v;
    __syncthreads();
    for (int o = SCAN_B / 2; o > 0; o >>= 1) {
        if (t < o) sh[t] += sh[t + o];
        __syncthreads();
    }
    if (t == 0) g_part[blockIdx.x] = sh[0];
}

// ---------------- scan stage 2: serial exclusive scan of partials ------------
__global__ void scan2_kernel() {
    if (threadIdx.x == 0) {
        int run = 0;
        for (int i = 0; i < SCAN_NB; i++) {
            int v = g_part[i];
            g_part[i] = run;
            run += v;
        }
    }
}

// ---------------- scan stage 3: padded exclusive scan + norm -----------------
__global__ void __launch_bounds__(SCAN_B) scan3_kernel(int N) {
    __shared__ int sh[SCAN_B];
    int t = threadIdx.x;
    int i = blockIdx.x * SCAN_B + t;
    int dv = (i < N) ? g_deg[i] : 0;
    int vp = (dv + 3) & ~3;
    sh[t] = vp;
    __syncthreads();
    for (int o = 1; o < SCAN_B; o <<= 1) {
        int a = (t >= o) ? sh[t - o] : 0;
        __syncthreads();
        sh[t] += a;
        __syncthreads();
    }
    if (i < N) {
        int excl = sh[t] - vp + g_part[blockIdx.x];
        g_off[i] = excl;
        g_cur[i] = excl;
        g_norm[i] = rsqrtf(fmaxf((float)dv, 1.0f));
    }
}

// ---------------- CSR fill: 4 edges/thread, independent atomic chains --------
__global__ void scatter_kernel(const int* __restrict__ src,
                               const int* __restrict__ dst, int E) {
    int t = blockIdx.x * blockDim.x + threadIdx.x;
    int e = t * 4;
    if (e + 4 <= E) {
        int4 s = __ldg((const int4*)(src + e));
        int4 d = __ldg((const int4*)(dst + e));
        int p0 = atomicAdd(&g_cur[d.x], 1);
        int p1 = atomicAdd(&g_cur[d.y], 1);
        int p2 = atomicAdd(&g_cur[d.z], 1);
        int p3 = atomicAdd(&g_cur[d.w], 1);
        g_csr[p0] = s.x;
        g_csr[p1] = s.y;
        g_csr[p2] = s.z;
        g_csr[p3] = s.w;
    } else {
        for (int k = e; k < E; k++) {
            int pos = atomicAdd(&g_cur[dst[k]], 1);
            g_csr[pos] = src[k];
        }
    }
}

// ---------------- y0h = fp16((x @ W) * norm)  via wmma -----------------------
// block: 64 rows x 64 cols, 8 warps in 4x2 grid, each warp 16x32 (2 frags)
__global__ void __launch_bounds__(256) gemm_kernel(const float* __restrict__ x,
                                                   const float* __restrict__ W,
                                                   int N) {
    __shared__ __half As[64][72];    // x tile (fp16), padded ld
    __shared__ __half Bs[64][72];    // W chunk [k][n]
    __shared__ float  Os[64][68];    // fp32 result staging

    const int t = threadIdx.x;
    const int w = t >> 5;
    const int wr = w >> 1;           // 0..3 (row group)
    const int wc = w & 1;            // 0..1 (col group)
    const int rowbase = blockIdx.x * 64;

    wmma::fragment<wmma::accumulator, 16, 16, 16, float> acc0, acc1;
    wmma::fill_fragment(acc0, 0.0f);
    wmma::fill_fragment(acc1, 0.0f);

    for (int kc = 0; kc < IN_F; kc += 64) {
        #pragma unroll
        for (int i = 0; i < 16; i++) {
            int lin = t + i * 256;
            int r = lin >> 6;
            int c = lin & 63;
            int gr = rowbase + r;
            float xv = (gr < N) ? x[(long long)gr * IN_F + kc + c] : 0.0f;
            As[r][c] = __float2half(xv);
            Bs[r][c] = __float2half(W[(kc + r) * OUT_F + c]);
        }
        __syncthreads();

        #pragma unroll
        for (int ks = 0; ks < 4; ks++) {
            wmma::fragment<wmma::matrix_a, 16, 16, 16, __half, wmma::row_major> af;
            wmma::load_matrix_sync(af, &As[wr * 16][ks * 16], 72);
            wmma::fragment<wmma::matrix_b, 16, 16, 16, __half, wmma::row_major> bf0, bf1;
            wmma::load_matrix_sync(bf0, &Bs[ks * 16][wc * 32], 72);
            wmma::load_matrix_sync(bf1, &Bs[ks * 16][wc * 32 + 16], 72);
            wmma::mma_sync(acc0, af, bf0, acc0);
            wmma::mma_sync(acc1, af, bf1, acc1);
        }
        __syncthreads();
    }

    wmma::store_matrix_sync(&Os[wr * 16][wc * 32], acc0, 68, wmma::mem_row_major);
    wmma::store_matrix_sync(&Os[wr * 16][wc * 32 + 16], acc1, 68, wmma::mem_row_major);
    __syncthreads();

    // scale by norm, convert to fp16, write (4 threads/row, 16 cols each)
    int r = t >> 2;
    int c0 = (t & 3) * 16;
    int gr = rowbase + r;
    if (gr < N) {
        float nm = g_norm[gr];
        __half2* p = (__half2*)&g_y0h[(long long)gr * OUT_F + c0];
        #pragma unroll
        for (int k = 0; k < 8; k++) {
            p[k] = __floats2half2_rn(Os[r][c0 + 2 * k] * nm,
                                     Os[r][c0 + 2 * k + 1] * nm);
        }
    }
}

// ---------------- pull round 1: z1h[i] = fp16((sum y0h[s]) * norm[i]^2) ------
// one warp per node; int4 index loads (rows padded to 4)
__global__ void __launch_bounds__(256) pull1_kernel(int N) {
    int warp = (blockIdx.x * blockDim.x + threadIdx.x) >> 5;
    if (warp >= N) return;
    int lane = threadIdx.x & 31;
    int base = g_off[warp];
    int deg = g_deg[warp];
    const __half2* yp = (const __half2*)g_y0h;
    const int* cp = g_csr + base;

    float ax = 0.0f, ay = 0.0f;
    int j = 0;
    for (; j + 4 <= deg; j += 4) {
        int4 s = __ldg((const int4*)(cp + j));
        float2 v0 = __half22float2(__ldg(yp + s.x * 32 + lane));
        float2 v1 = __half22float2(__ldg(yp + s.y * 32 + lane));
        float2 v2 = __half22float2(__ldg(yp + s.z * 32 + lane));
        float2 v3 = __half22float2(__ldg(yp + s.w * 32 + lane));
        ax += v0.x + v1.x + v2.x + v3.x;
        ay += v0.y + v1.y + v2.y + v3.y;
    }
    if (j < deg) {
        int4 s = __ldg((const int4*)(cp + j));  // padded row: in-bounds
        {            float2 v = __half22float2(__ldg(yp + s.x * 32 + lane)); ax += v.x; ay += v.y; }
        if (j + 1 < deg) { float2 v = __half22float2(__ldg(yp + s.y * 32 + lane)); ax += v.x; ay += v.y; }
        if (j + 2 < deg) { float2 v = __half22float2(__ldg(yp + s.z * 32 + lane)); ax += v.x; ay += v.y; }
    }
    float nm = g_norm[warp];
    nm *= nm;
    ((__half2*)g_z1h)[warp * 32 + lane] = __floats2half2_rn(ax * nm, ay * nm);
}

// ---------------- pull round 2: out[i] = (sum z1h[s]) * norm[i] + b ----------
__global__ void __launch_bounds__(256) pull2_kernel(const float* __restrict__ b,
                                                    float* __restrict__ out, int N) {
    int warp = (blockIdx.x * blockDim.x + threadIdx.x) >> 5;
    if (warp >= N) return;
    int lane = threadIdx.x & 31;
    int base = g_off[warp];
    int deg = g_deg[warp];
    const __half2* zp = (const __half2*)g_z1h;
    const int* cp = g_csr + base;

    float ax = 0.0f, ay = 0.0f;
    int j = 0;
    for (; j + 4 <= deg; j += 4) {
        int4 s = __ldg((const int4*)(cp + j));
        float2 v0 = __half22float2(__ldg(zp + s.x * 32 + lane));
        float2 v1 = __half22float2(__ldg(zp + s.y * 32 + lane));
        float2 v2 = __half22float2(__ldg(zp + s.z * 32 + lane));
        float2 v3 = __half22float2(__ldg(zp + s.w * 32 + lane));
        ax += v0.x + v1.x + v2.x + v3.x;
        ay += v0.y + v1.y + v2.y + v3.y;
    }
    if (j < deg) {
        int4 s = __ldg((const int4*)(cp + j));
        {            float2 v = __half22float2(__ldg(zp + s.x * 32 + lane)); ax += v.x; ay += v.y; }
        if (j + 1 < deg) { float2 v = __half22float2(__ldg(zp + s.y * 32 + lane)); ax += v.x; ay += v.y; }
        if (j + 2 < deg) { float2 v = __half22float2(__ldg(zp + s.z * 32 + lane)); ax += v.x; ay += v.y; }
    }
    float nm = g_norm[warp];
    float2 bb = __ldg((const float2*)b + lane);
    ((float2*)out)[warp * 32 + lane] =
        make_float2(ax * nm + bb.x, ay * nm + bb.y);
}

// ---------------- launch -----------------------------------------------------
extern "C" void kernel_launch(void* const* d_in, const int* in_sizes, int n_in,
                              void* d_out, int out_size) {
    const float* x   = (const float*)d_in[0];
    const int*   src = (const int*)d_in[1];
    const int*   dst = (const int*)d_in[2];
    const float* W   = (const float*)d_in[3];
    const float* b   = (const float*)d_in[4];
    float*       out = (float*)d_out;

    const int N = in_sizes[0] / IN_F;   // 100000
    const int E = in_sizes[1];          // 3200000

    void* p_deg;
    cudaGetSymbolAddress(&p_deg, g_deg);
    cudaMemsetAsync(p_deg, 0, (size_t)N * sizeof(int));

    // CSR build (padded rows); 4 edges/thread in deg & scatter
    const int et = (E + 3) / 4;
    deg_kernel<<<(et + 255) / 256, 256>>>(dst, E);
    scan1_kernel<<<SCAN_NB, SCAN_B>>>(N);
    scan2_kernel<<<1, 32>>>();
    scan3_kernel<<<SCAN_NB, SCAN_B>>>(N);
    scatter_kernel<<<(et + 255) / 256, 256>>>(src, dst, E);

    // tensor-core projection (scaled by norm at write, fp16 out)
    gemm_kernel<<<(N + 63) / 64, 256>>>(x, W, N);

    // two pull rounds (warp per node)
    const int pb = 256;
    const int pgrid = (N * 32 + pb - 1) / pb;
    pull1_kernel<<<pgrid, pb>>>(N);
    pull2_kernel<<<pgrid, pb>>>(b, out, N);
}